// round 1
// baseline (speedup 1.0000x reference)
#include <cuda_runtime.h>
#include <cuda_bf16.h>
#include <cstdint>

#define B_  4
#define S_  1024
#define E_  1024
#define H_  16
#define HD_ 64
// N for qkv gemm
#define N3E 3072

// ---------------- scratch (device globals; no allocation allowed) ----------------
__device__ float g_Q[(size_t)B_ * H_ * S_ * HD_];   // 16 MB
__device__ float g_K[(size_t)B_ * H_ * S_ * HD_];   // 16 MB
__device__ float g_V[(size_t)B_ * H_ * S_ * HD_];   // 16 MB
__device__ float g_P[(size_t)B_ * H_ * S_ * S_];    // 256 MB
__device__ float g_O[(size_t)B_ * S_ * E_];         // 16 MB
__device__ int   g_mask_kind;                        // 0=int32, 1=uint8, 2=float32

// ---------------- mask dtype detection ----------------
// mask comes from jnp bool -> unknown serialized dtype. Classify from bit patterns:
//  int32 {0,1}    : words in {0,1}
//  uint8 {0,1}    : words have set bytes above byte0 w.h.p.
//  float32 {0,1.f}: some word == 0x3F800000 w.h.p.
__global__ void detect_mask_kind_kernel(const unsigned int* __restrict__ mw) {
    if (threadIdx.x == 0 && blockIdx.x == 0) {
        int kind = 0;
        for (int i = 0; i < 256; i++) {
            unsigned int w = mw[i];
            if (w == 0x3F800000u) { kind = 2; break; }
            if (w > 1u) kind = 1;
        }
        g_mask_kind = kind;
    }
}

// ---------------- GEMM 1: qkv = x @ qkv_w^T + b, scatter into Q/K/V ----------------
// x: [4096, 1024] row-major. W: [3072, 1024] row-major. NT gemm (both K-major).
// BM=BN=128, BK=16, 256 threads, 8x8 per thread.
__global__ __launch_bounds__(256)
void qkv_gemm_kernel(const float* __restrict__ X, const float* __restrict__ W,
                     const float* __restrict__ bias) {
    const int K = 1024;
    __shared__ float As[16][132];
    __shared__ float Bs[16][132];

    const int tid = threadIdx.x;
    const int tx = tid & 15, ty = tid >> 4;
    const int row0 = blockIdx.y * 128;
    const int col0 = blockIdx.x * 128;

    float acc[8][8];
#pragma unroll
    for (int i = 0; i < 8; i++)
#pragma unroll
        for (int j = 0; j < 8; j++) acc[i][j] = 0.f;

    for (int kk = 0; kk < K / 16; kk++) {
#pragma unroll
        for (int i = 0; i < 2; i++) {
            int f = tid + i * 256;           // 0..511 float4 slots
            int r = f >> 2, q = f & 3;
            float4 av = *reinterpret_cast<const float4*>(
                &X[(size_t)(row0 + r) * K + kk * 16 + q * 4]);
            As[q * 4 + 0][r] = av.x; As[q * 4 + 1][r] = av.y;
            As[q * 4 + 2][r] = av.z; As[q * 4 + 3][r] = av.w;
            float4 bv = *reinterpret_cast<const float4*>(
                &W[(size_t)(col0 + r) * K + kk * 16 + q * 4]);
            Bs[q * 4 + 0][r] = bv.x; Bs[q * 4 + 1][r] = bv.y;
            Bs[q * 4 + 2][r] = bv.z; Bs[q * 4 + 3][r] = bv.w;
        }
        __syncthreads();
#pragma unroll
        for (int k = 0; k < 16; k++) {
            float4 a0 = *reinterpret_cast<const float4*>(&As[k][ty * 8]);
            float4 a1 = *reinterpret_cast<const float4*>(&As[k][ty * 8 + 4]);
            float4 b0 = *reinterpret_cast<const float4*>(&Bs[k][tx * 8]);
            float4 b1 = *reinterpret_cast<const float4*>(&Bs[k][tx * 8 + 4]);
            float a[8] = {a0.x, a0.y, a0.z, a0.w, a1.x, a1.y, a1.z, a1.w};
            float b[8] = {b0.x, b0.y, b0.z, b0.w, b1.x, b1.y, b1.z, b1.w};
#pragma unroll
            for (int i = 0; i < 8; i++)
#pragma unroll
                for (int j = 0; j < 8; j++) acc[i][j] = fmaf(a[i], b[j], acc[i][j]);
        }
        __syncthreads();
    }

    // Epilogue: interleaved head split. col n -> h = n/192, r = n%192, part = r/64, d = r%64
#pragma unroll
    for (int i = 0; i < 8; i++) {
        int m = row0 + ty * 8 + i;
        int bidx = m >> 10;          // m / S
        int s = m & 1023;            // m % S
#pragma unroll
        for (int j = 0; j < 8; j++) {
            int n = col0 + tx * 8 + j;
            float v = acc[i][j] + bias[n];
            int h = n / 192;
            int r = n - h * 192;
            int part = r >> 6;
            int d = r & 63;
            size_t o = (((size_t)bidx * H_ + h) * S_ + s) * HD_ + d;
            if (part == 0) g_Q[o] = v;
            else if (part == 1) g_K[o] = v;
            else g_V[o] = v;
        }
    }
}

// ---------------- GEMM 2: logits = Q K^T / 32 + prev, mask -> -1e30 ----------------
// batched over g = b*H + h (64 batches). A=Q[g] [1024,64], B=K[g] [1024,64], K-dim 64.
__global__ __launch_bounds__(256)
void scores_gemm_kernel(const float* __restrict__ prev, const void* __restrict__ mask) {
    const int K = 64;
    __shared__ float As[16][132];
    __shared__ float Bs[16][132];

    const int tid = threadIdx.x;
    const int tx = tid & 15, ty = tid >> 4;
    const int g = blockIdx.z;
    const int row0 = blockIdx.y * 128;
    const int col0 = blockIdx.x * 128;
    const float* A = g_Q + (size_t)g * S_ * HD_;
    const float* Bm = g_K + (size_t)g * S_ * HD_;

    float acc[8][8];
#pragma unroll
    for (int i = 0; i < 8; i++)
#pragma unroll
        for (int j = 0; j < 8; j++) acc[i][j] = 0.f;

    for (int kk = 0; kk < K / 16; kk++) {
#pragma unroll
        for (int i = 0; i < 2; i++) {
            int f = tid + i * 256;
            int r = f >> 2, q = f & 3;
            float4 av = *reinterpret_cast<const float4*>(
                &A[(size_t)(row0 + r) * K + kk * 16 + q * 4]);
            As[q * 4 + 0][r] = av.x; As[q * 4 + 1][r] = av.y;
            As[q * 4 + 2][r] = av.z; As[q * 4 + 3][r] = av.w;
            float4 bv = *reinterpret_cast<const float4*>(
                &Bm[(size_t)(col0 + r) * K + kk * 16 + q * 4]);
            Bs[q * 4 + 0][r] = bv.x; Bs[q * 4 + 1][r] = bv.y;
            Bs[q * 4 + 2][r] = bv.z; Bs[q * 4 + 3][r] = bv.w;
        }
        __syncthreads();
#pragma unroll
        for (int k = 0; k < 16; k++) {
            float4 a0 = *reinterpret_cast<const float4*>(&As[k][ty * 8]);
            float4 a1 = *reinterpret_cast<const float4*>(&As[k][ty * 8 + 4]);
            float4 b0 = *reinterpret_cast<const float4*>(&Bs[k][tx * 8]);
            float4 b1 = *reinterpret_cast<const float4*>(&Bs[k][tx * 8 + 4]);
            float a[8] = {a0.x, a0.y, a0.z, a0.w, a1.x, a1.y, a1.z, a1.w};
            float b[8] = {b0.x, b0.y, b0.z, b0.w, b1.x, b1.y, b1.z, b1.w};
#pragma unroll
            for (int i = 0; i < 8; i++)
#pragma unroll
                for (int j = 0; j < 8; j++) acc[i][j] = fmaf(a[i], b[j], acc[i][j]);
        }
        __syncthreads();
    }

    const int kind = g_mask_kind;
    const int* mi = (const int*)mask;
    const unsigned char* mb = (const unsigned char*)mask;
    const float* mf = (const float*)mask;

#pragma unroll
    for (int i = 0; i < 8; i++) {
        int m = row0 + ty * 8 + i;
#pragma unroll
        for (int j = 0; j < 8; j++) {
            int n = col0 + tx * 8 + j;
            size_t base = ((size_t)g * S_ + m) * S_ + n;
            size_t midx = (size_t)m * S_ + n;
            float v = acc[i][j] * 0.03125f + prev[base];
            bool msk;
            if (kind == 0)      msk = mi[midx] != 0;
            else if (kind == 1) msk = mb[midx] != 0;
            else                msk = mf[midx] != 0.f;
            g_P[base] = msk ? -1e30f : v;
        }
    }
}

// ---------------- softmax: one warp per row of 1024 ----------------
__global__ __launch_bounds__(256)
void softmax_kernel() {
    const int warp = threadIdx.x >> 5;
    const int lane = threadIdx.x & 31;
    size_t row = (size_t)blockIdx.x * 8 + warp;
    float4* p = reinterpret_cast<float4*>(g_P + row * S_);

    float4 v[8];
    float mx = -1e38f;
#pragma unroll
    for (int i = 0; i < 8; i++) {
        v[i] = p[i * 32 + lane];
        mx = fmaxf(mx, fmaxf(fmaxf(v[i].x, v[i].y), fmaxf(v[i].z, v[i].w)));
    }
#pragma unroll
    for (int o = 16; o > 0; o >>= 1)
        mx = fmaxf(mx, __shfl_xor_sync(0xffffffffu, mx, o));

    float sum = 0.f;
#pragma unroll
    for (int i = 0; i < 8; i++) {
        v[i].x = __expf(v[i].x - mx); v[i].y = __expf(v[i].y - mx);
        v[i].z = __expf(v[i].z - mx); v[i].w = __expf(v[i].w - mx);
        sum += v[i].x + v[i].y + v[i].z + v[i].w;
    }
#pragma unroll
    for (int o = 16; o > 0; o >>= 1)
        sum += __shfl_xor_sync(0xffffffffu, sum, o);

    float inv = 1.f / sum;
#pragma unroll
    for (int i = 0; i < 8; i++) {
        v[i].x *= inv; v[i].y *= inv; v[i].z *= inv; v[i].w *= inv;
        p[i * 32 + lane] = v[i];
    }
}

// ---------------- GEMM 3: O = P @ V (NN, N=64), batched over g ----------------
// BM=128, BN=64, BK=16, 256 threads, 8x4 per thread.
__global__ __launch_bounds__(256)
void pv_gemm_kernel() {
    const int K = 1024;
    __shared__ float As[16][132];
    __shared__ float Bs[16][68];

    const int tid = threadIdx.x;
    const int tx = tid & 15, ty = tid >> 4;
    const int g = blockIdx.y;
    const int row0 = blockIdx.x * 128;
    const float* A = g_P + (size_t)g * S_ * S_;
    const float* Bm = g_V + (size_t)g * S_ * HD_;

    float acc[8][4];
#pragma unroll
    for (int i = 0; i < 8; i++)
#pragma unroll
        for (int j = 0; j < 4; j++) acc[i][j] = 0.f;

    for (int kk = 0; kk < K / 16; kk++) {
        // A tile 128x16, transposed store
#pragma unroll
        for (int i = 0; i < 2; i++) {
            int f = tid + i * 256;
            int r = f >> 2, q = f & 3;
            float4 av = *reinterpret_cast<const float4*>(
                &A[(size_t)(row0 + r) * K + kk * 16 + q * 4]);
            As[q * 4 + 0][r] = av.x; As[q * 4 + 1][r] = av.y;
            As[q * 4 + 2][r] = av.z; As[q * 4 + 3][r] = av.w;
        }
        // B tile 16x64, direct store (k-major rows)
        {
            int r = tid >> 4, q = tid & 15;
            float4 bv = *reinterpret_cast<const float4*>(
                &Bm[(size_t)(kk * 16 + r) * HD_ + q * 4]);
            *reinterpret_cast<float4*>(&Bs[r][q * 4]) = bv;
        }
        __syncthreads();
#pragma unroll
        for (int k = 0; k < 16; k++) {
            float4 a0 = *reinterpret_cast<const float4*>(&As[k][ty * 8]);
            float4 a1 = *reinterpret_cast<const float4*>(&As[k][ty * 8 + 4]);
            float4 b0 = *reinterpret_cast<const float4*>(&Bs[k][tx * 4]);
            float a[8] = {a0.x, a0.y, a0.z, a0.w, a1.x, a1.y, a1.z, a1.w};
            float b[4] = {b0.x, b0.y, b0.z, b0.w};
#pragma unroll
            for (int i = 0; i < 8; i++)
#pragma unroll
                for (int j = 0; j < 4; j++) acc[i][j] = fmaf(a[i], b[j], acc[i][j]);
        }
        __syncthreads();
    }

    const int bidx = g >> 4;     // g / H
    const int h = g & 15;        // g % H
#pragma unroll
    for (int i = 0; i < 8; i++) {
        int m = row0 + ty * 8 + i;   // s index
#pragma unroll
        for (int j = 0; j < 4; j++) {
            int d = tx * 4 + j;
            g_O[((size_t)bidx * S_ + m) * E_ + h * HD_ + d] = acc[i][j];
        }
    }
}

// ---------------- GEMM 4: out = O @ o_w^T + o_b ----------------
__global__ __launch_bounds__(256)
void out_gemm_kernel(const float* __restrict__ W, const float* __restrict__ bias,
                     float* __restrict__ out) {
    const int K = 1024;
    __shared__ float As[16][132];
    __shared__ float Bs[16][132];

    const int tid = threadIdx.x;
    const int tx = tid & 15, ty = tid >> 4;
    const int row0 = blockIdx.y * 128;
    const int col0 = blockIdx.x * 128;

    float acc[8][8];
#pragma unroll
    for (int i = 0; i < 8; i++)
#pragma unroll
        for (int j = 0; j < 8; j++) acc[i][j] = 0.f;

    for (int kk = 0; kk < K / 16; kk++) {
#pragma unroll
        for (int i = 0; i < 2; i++) {
            int f = tid + i * 256;
            int r = f >> 2, q = f & 3;
            float4 av = *reinterpret_cast<const float4*>(
                &g_O[(size_t)(row0 + r) * K + kk * 16 + q * 4]);
            As[q * 4 + 0][r] = av.x; As[q * 4 + 1][r] = av.y;
            As[q * 4 + 2][r] = av.z; As[q * 4 + 3][r] = av.w;
            float4 bv = *reinterpret_cast<const float4*>(
                &W[(size_t)(col0 + r) * K + kk * 16 + q * 4]);
            Bs[q * 4 + 0][r] = bv.x; Bs[q * 4 + 1][r] = bv.y;
            Bs[q * 4 + 2][r] = bv.z; Bs[q * 4 + 3][r] = bv.w;
        }
        __syncthreads();
#pragma unroll
        for (int k = 0; k < 16; k++) {
            float4 a0 = *reinterpret_cast<const float4*>(&As[k][ty * 8]);
            float4 a1 = *reinterpret_cast<const float4*>(&As[k][ty * 8 + 4]);
            float4 b0 = *reinterpret_cast<const float4*>(&Bs[k][tx * 8]);
            float4 b1 = *reinterpret_cast<const float4*>(&Bs[k][tx * 8 + 4]);
            float a[8] = {a0.x, a0.y, a0.z, a0.w, a1.x, a1.y, a1.z, a1.w};
            float b[8] = {b0.x, b0.y, b0.z, b0.w, b1.x, b1.y, b1.z, b1.w};
#pragma unroll
            for (int i = 0; i < 8; i++)
#pragma unroll
                for (int j = 0; j < 8; j++) acc[i][j] = fmaf(a[i], b[j], acc[i][j]);
        }
        __syncthreads();
    }

#pragma unroll
    for (int i = 0; i < 8; i++) {
        int m = row0 + ty * 8 + i;
#pragma unroll
        for (int j = 0; j < 8; j++) {
            int n = col0 + tx * 8 + j;
            out[(size_t)m * E_ + n] = acc[i][j] + bias[n];
        }
    }
}

// ---------------- launch ----------------
extern "C" void kernel_launch(void* const* d_in, const int* in_sizes, int n_in,
                              void* d_out, int out_size) {
    const float* x     = (const float*)d_in[0];
    const void*  mask  = d_in[1];
    const float* prev  = (const float*)d_in[2];
    const float* qkv_w = (const float*)d_in[3];
    const float* qkv_b = (const float*)d_in[4];
    const float* o_w   = (const float*)d_in[5];
    const float* o_b   = (const float*)d_in[6];
    float* out = (float*)d_out;

    detect_mask_kind_kernel<<<1, 32>>>((const unsigned int*)mask);

    // qkv: M=4096, N=3072
    qkv_gemm_kernel<<<dim3(N3E / 128, (B_ * S_) / 128), 256>>>(x, qkv_w, qkv_b);

    // scores: per batch g in [0,64): 1024x1024, K=64
    scores_gemm_kernel<<<dim3(S_ / 128, S_ / 128, B_ * H_), 256>>>(prev, mask);

    // softmax: 65536 rows, 8 rows/block
    softmax_kernel<<<(B_ * H_ * S_) / 8, 256>>>();

    // PV: per batch g: 1024x64, K=1024
    pv_gemm_kernel<<<dim3(S_ / 128, B_ * H_), 256>>>();

    // out proj: M=4096, N=1024
    out_gemm_kernel<<<dim3(E_ / 128, (B_ * S_) / 128), 256>>>(o_w, o_b, out);
}

// round 3
// speedup vs baseline: 2.1776x; 2.1776x over previous
#include <cuda_runtime.h>
#include <cstdint>

#define B_  4
#define S_  1024
#define E_  1024
#define H_  16
#define HD_ 64
#define N3E 3072
#define LDS_PAD 36   // floats per smem row (BK=32 + 4 pad): conflict-free, 16B-aligned

// ---------------- scratch ----------------
__device__ float g_Q [(size_t)B_ * H_ * S_ * HD_];
__device__ float g_K [(size_t)B_ * H_ * S_ * HD_];
__device__ float g_V [(size_t)B_ * H_ * S_ * HD_];
__device__ float g_Vt[(size_t)B_ * H_ * S_ * HD_];   // [g][d][s]
__device__ float g_P [(size_t)B_ * H_ * S_ * S_];
__device__ float g_O [(size_t)B_ * S_ * E_];
__device__ int   g_mask_kind;

// ---------------- helpers ----------------
__device__ __forceinline__ uint32_t smem_u32(const void* p) {
    uint32_t a;
    asm("{ .reg .u64 t; cvta.to.shared.u64 t, %1; cvt.u32.u64 %0, t; }"
        : "=r"(a) : "l"(p));
    return a;
}
__device__ __forceinline__ uint32_t cvt_tf32(float x) {
    uint32_t u; asm("cvt.rna.tf32.f32 %0, %1;" : "=r"(u) : "f"(x)); return u;
}
__device__ __forceinline__ void ldsm4(uint32_t* r, uint32_t addr) {
    asm volatile("ldmatrix.sync.aligned.m8n8.x4.shared.b16 {%0,%1,%2,%3}, [%4];"
                 : "=r"(r[0]), "=r"(r[1]), "=r"(r[2]), "=r"(r[3]) : "r"(addr));
}
__device__ __forceinline__ void mma8(float* c, const uint32_t* a, const uint32_t* b) {
    asm volatile(
        "mma.sync.aligned.m16n8k8.row.col.f32.tf32.tf32.f32 "
        "{%0,%1,%2,%3}, {%4,%5,%6,%7}, {%8,%9}, {%0,%1,%2,%3};"
        : "+f"(c[0]), "+f"(c[1]), "+f"(c[2]), "+f"(c[3])
        : "r"(a[0]), "r"(a[1]), "r"(a[2]), "r"(a[3]), "r"(b[0]), "r"(b[1]));
}

// ---------------- mainloop: C[128,BN] = A[128,K] @ B[BN,K]^T (both K-major) ----------------
// 256 threads. Warp grid WM x WN. Warp tile: (128/WM) x (BN/WN). tf32 m16n8k8.
template<int BN, int WM, int WN>
__device__ __forceinline__ void gemm_mainloop(
    const float* __restrict__ A, int lda,
    const float* __restrict__ Bm, int ldb, int K,
    float* sA, float* sB, float* acc)   // acc[MT*NT*4]
{
    constexpr int MT = 128 / (WM * 16);
    constexpr int NT = BN / (WN * 8);
    const int tid = threadIdx.x;
    const int warp = tid >> 5, lane = tid & 31;
    const int wm = warp % WM, wn = warp / WM;
    const int m0 = wm * MT * 16;
    const int n0 = wn * NT * 8;

    const uint32_t sa_base = smem_u32(sA);
    const uint32_t sb_base = smem_u32(sB);

    // ldmatrix per-lane row/col offsets
    const int a_row = (lane & 7) + ((lane & 8) ? 8 : 0);   // mats 0/2: +0, 1/3: +8
    const int a_k   = (lane & 16) ? 4 : 0;                 // mats 0/1: k, 2/3: k+4
    const int b_row = (lane & 7) + ((lane & 16) ? 8 : 0);  // mats 0/1: n+0..7, 2/3: n+8..15
    const int b_k   = (lane & 8) ? 4 : 0;                  // mats 0/2: k, 1/3: k+4

    const int nch = K >> 5;
    for (int kc = 0; kc < nch; kc++) {
        // ---- global -> shared (tf32-rounded) ----
#pragma unroll
        for (int i = 0; i < (128 * 8) / 256; i++) {
            int f = tid + i * 256;
            int r = f >> 3, q = f & 7;
            float4 v = *reinterpret_cast<const float4*>(
                &A[(size_t)r * lda + (kc << 5) + (q << 2)]);
            uint4 u;
            u.x = cvt_tf32(v.x); u.y = cvt_tf32(v.y);
            u.z = cvt_tf32(v.z); u.w = cvt_tf32(v.w);
            *reinterpret_cast<uint4*>(&sA[r * LDS_PAD + (q << 2)]) = u;
        }
#pragma unroll
        for (int i = 0; i < (BN * 8) / 256; i++) {
            int f = tid + i * 256;
            int r = f >> 3, q = f & 7;
            float4 v = *reinterpret_cast<const float4*>(
                &Bm[(size_t)r * ldb + (kc << 5) + (q << 2)]);
            uint4 u;
            u.x = cvt_tf32(v.x); u.y = cvt_tf32(v.y);
            u.z = cvt_tf32(v.z); u.w = cvt_tf32(v.w);
            *reinterpret_cast<uint4*>(&sB[r * LDS_PAD + (q << 2)]) = u;
        }
        __syncthreads();

        // ---- 4 k-steps of m16n8k8 ----
#pragma unroll
        for (int ks = 0; ks < 4; ks++) {
            const int kk = ks << 3;
            uint32_t afr[MT][4];
#pragma unroll
            for (int mt = 0; mt < MT; mt++) {
                uint32_t addr = sa_base +
                    (uint32_t)(((m0 + mt * 16 + a_row) * LDS_PAD + kk + a_k) << 2);
                ldsm4(afr[mt], addr);
            }
            uint32_t bfr[NT][2];
#pragma unroll
            for (int np = 0; np < NT / 2; np++) {
                uint32_t r[4];
                uint32_t addr = sb_base +
                    (uint32_t)(((n0 + np * 16 + b_row) * LDS_PAD + kk + b_k) << 2);
                ldsm4(r, addr);
                bfr[np * 2 + 0][0] = r[0]; bfr[np * 2 + 0][1] = r[1];
                bfr[np * 2 + 1][0] = r[2]; bfr[np * 2 + 1][1] = r[3];
            }
#pragma unroll
            for (int mt = 0; mt < MT; mt++)
#pragma unroll
                for (int nt = 0; nt < NT; nt++)
                    mma8(&acc[(mt * NT + nt) * 4], afr[mt], bfr[nt]);
        }
        __syncthreads();
    }
}

// ---------------- mask dtype detection ----------------
__global__ void detect_mask_kind_kernel(const unsigned int* __restrict__ mw) {
    if (threadIdx.x == 0 && blockIdx.x == 0) {
        int kind = 0;
        for (int i = 0; i < 256; i++) {
            unsigned int w = mw[i];
            if (w == 0x3F800000u) { kind = 2; break; }
            if (w > 1u) kind = 1;
        }
        g_mask_kind = kind;
    }
}

// ---------------- kernel 1: QKV = X @ W^T + b, scatter Q/K/V ----------------
__global__ __launch_bounds__(256, 2)
void qkv_mma_kernel(const float* __restrict__ X, const float* __restrict__ W,
                    const float* __restrict__ bias) {
    constexpr int BN = 128, WM = 2, WN = 4;
    constexpr int MT = 4, NT = 4;
    __shared__ float sA[128 * LDS_PAD];
    __shared__ float sB[BN * LDS_PAD];
    float acc[MT * NT * 4];
#pragma unroll
    for (int i = 0; i < MT * NT * 4; i++) acc[i] = 0.f;

    const int row0 = blockIdx.y * 128;
    const int col0 = blockIdx.x * 128;
    gemm_mainloop<BN, WM, WN>(X + (size_t)row0 * E_, E_,
                              W + (size_t)col0 * E_, E_, E_, sA, sB, acc);

    const int tid = threadIdx.x;
    const int warp = tid >> 5, lane = tid & 31;
    const int wm = warp % WM, wn = warp / WM;

#pragma unroll
    for (int mt = 0; mt < MT; mt++) {
#pragma unroll
        for (int nt = 0; nt < NT; nt++) {
            const float* c = &acc[(mt * NT + nt) * 4];
            int n = col0 + wn * 32 + nt * 8 + 2 * (lane & 3);
            int h = n / 192;
            int rr = n - h * 192;
            int part = rr >> 6;
            int d = rr & 63;
            float* dst = (part == 0) ? g_Q : ((part == 1) ? g_K : g_V);
            float b0 = bias[n], b1 = bias[n + 1];
#pragma unroll
            for (int half = 0; half < 2; half++) {
                int m = row0 + wm * 64 + mt * 16 + (lane >> 2) + half * 8;
                int bidx = m >> 10;
                int s = m & 1023;
                float2 v = make_float2(c[half * 2 + 0] + b0, c[half * 2 + 1] + b1);
                *reinterpret_cast<float2*>(
                    &dst[(((size_t)bidx * H_ + h) * S_ + s) * HD_ + d]) = v;
            }
        }
    }
}

// ---------------- V transpose: Vt[g][d][s] = V[g][s][d] ----------------
__global__ void vt_kernel() {
    __shared__ float t[32][33];
    int g = blockIdx.z;
    int s0 = blockIdx.y * 32, d0 = blockIdx.x * 32;
    const float* V = g_V + (size_t)g * S_ * HD_;
    float* Vt = g_Vt + (size_t)g * HD_ * S_;
    for (int i = threadIdx.y; i < 32; i += 8)
        t[i][threadIdx.x] = V[(size_t)(s0 + i) * HD_ + d0 + threadIdx.x];
    __syncthreads();
    for (int i = threadIdx.y; i < 32; i += 8)
        Vt[(size_t)(d0 + i) * S_ + s0 + threadIdx.x] = t[threadIdx.x][i];
}

// ---------------- kernel 2: P = QK^T/32 + prev, masked ----------------
__global__ __launch_bounds__(256, 2)
void scores_mma_kernel(const float* __restrict__ prev, const void* __restrict__ mask) {
    constexpr int BN = 128, WM = 2, WN = 4;
    constexpr int MT = 4, NT = 4;
    __shared__ float sA[128 * LDS_PAD];
    __shared__ float sB[BN * LDS_PAD];
    float acc[MT * NT * 4];
#pragma unroll
    for (int i = 0; i < MT * NT * 4; i++) acc[i] = 0.f;

    const int g = blockIdx.z;
    const int row0 = blockIdx.y * 128;
    const int col0 = blockIdx.x * 128;
    gemm_mainloop<BN, WM, WN>(g_Q + (size_t)g * S_ * HD_ + (size_t)row0 * HD_, HD_,
                              g_K + (size_t)g * S_ * HD_ + (size_t)col0 * HD_, HD_,
                              HD_, sA, sB, acc);

    const int tid = threadIdx.x;
    const int warp = tid >> 5, lane = tid & 31;
    const int wm = warp % WM, wn = warp / WM;
    const int kind = g_mask_kind;
    const int* mi = (const int*)mask;
    const unsigned char* mb = (const unsigned char*)mask;
    const float* mf = (const float*)mask;

#pragma unroll
    for (int mt = 0; mt < MT; mt++) {
#pragma unroll
        for (int nt = 0; nt < NT; nt++) {
            const float* c = &acc[(mt * NT + nt) * 4];
            int n = col0 + wn * 32 + nt * 8 + 2 * (lane & 3);
#pragma unroll
            for (int half = 0; half < 2; half++) {
                int m = row0 + wm * 64 + mt * 16 + (lane >> 2) + half * 8;
                size_t pidx = ((size_t)g * S_ + m) * S_ + n;
                size_t midx = (size_t)m * S_ + n;
                float2 pv = *reinterpret_cast<const float2*>(&prev[pidx]);
                bool k0, k1;
                if (kind == 0)      { k0 = mi[midx] != 0;       k1 = mi[midx + 1] != 0; }
                else if (kind == 1) { k0 = mb[midx] != 0;       k1 = mb[midx + 1] != 0; }
                else                { k0 = mf[midx] != 0.f;     k1 = mf[midx + 1] != 0.f; }
                float2 v;
                v.x = k0 ? -1e30f : fmaf(c[half * 2 + 0], 0.03125f, pv.x);
                v.y = k1 ? -1e30f : fmaf(c[half * 2 + 1], 0.03125f, pv.y);
                *reinterpret_cast<float2*>(&g_P[pidx]) = v;
            }
        }
    }
}

// ---------------- softmax ----------------
__global__ __launch_bounds__(256)
void softmax_kernel() {
    const int warp = threadIdx.x >> 5;
    const int lane = threadIdx.x & 31;
    size_t row = (size_t)blockIdx.x * 8 + warp;
    float4* p = reinterpret_cast<float4*>(g_P + row * S_);

    float4 v[8];
    float mx = -1e38f;
#pragma unroll
    for (int i = 0; i < 8; i++) {
        v[i] = p[i * 32 + lane];
        mx = fmaxf(mx, fmaxf(fmaxf(v[i].x, v[i].y), fmaxf(v[i].z, v[i].w)));
    }
#pragma unroll
    for (int o = 16; o > 0; o >>= 1)
        mx = fmaxf(mx, __shfl_xor_sync(0xffffffffu, mx, o));

    float sum = 0.f;
#pragma unroll
    for (int i = 0; i < 8; i++) {
        v[i].x = __expf(v[i].x - mx); v[i].y = __expf(v[i].y - mx);
        v[i].z = __expf(v[i].z - mx); v[i].w = __expf(v[i].w - mx);
        sum += v[i].x + v[i].y + v[i].z + v[i].w;
    }
#pragma unroll
    for (int o = 16; o > 0; o >>= 1)
        sum += __shfl_xor_sync(0xffffffffu, sum, o);

    float inv = 1.f / sum;
#pragma unroll
    for (int i = 0; i < 8; i++) {
        v[i].x *= inv; v[i].y *= inv; v[i].z *= inv; v[i].w *= inv;
        p[i * 32 + lane] = v[i];
    }
}

// ---------------- kernel 3: O = P @ V (via Vt, NT) ----------------
__global__ __launch_bounds__(256, 2)
void pv_mma_kernel() {
    constexpr int BN = 64, WM = 4, WN = 2;
    constexpr int MT = 2, NT = 4;
    __shared__ float sA[128 * LDS_PAD];
    __shared__ float sB[BN * LDS_PAD];
    float acc[MT * NT * 4];
#pragma unroll
    for (int i = 0; i < MT * NT * 4; i++) acc[i] = 0.f;

    const int g = blockIdx.y;
    const int row0 = blockIdx.x * 128;
    gemm_mainloop<BN, WM, WN>(g_P + (size_t)g * S_ * S_ + (size_t)row0 * S_, S_,
                              g_Vt + (size_t)g * HD_ * S_, S_, S_, sA, sB, acc);

    const int tid = threadIdx.x;
    const int warp = tid >> 5, lane = tid & 31;
    const int wm = warp % WM, wn = warp / WM;
    const int bidx = g >> 4;
    const int h = g & 15;

#pragma unroll
    for (int mt = 0; mt < MT; mt++) {
#pragma unroll
        for (int nt = 0; nt < NT; nt++) {
            const float* c = &acc[(mt * NT + nt) * 4];
            int d = wn * 32 + nt * 8 + 2 * (lane & 3);
#pragma unroll
            for (int half = 0; half < 2; half++) {
                int s = row0 + wm * 32 + mt * 16 + (lane >> 2) + half * 8;
                float2 v = make_float2(c[half * 2 + 0], c[half * 2 + 1]);
                *reinterpret_cast<float2*>(
                    &g_O[((size_t)bidx * S_ + s) * E_ + h * HD_ + d]) = v;
            }
        }
    }
}

// ---------------- kernel 4: out = O @ o_w^T + o_b ----------------
__global__ __launch_bounds__(256, 2)
void out_mma_kernel(const float* __restrict__ W, const float* __restrict__ bias,
                    float* __restrict__ out) {
    constexpr int BN = 128, WM = 2, WN = 4;
    constexpr int MT = 4, NT = 4;
    __shared__ float sA[128 * LDS_PAD];
    __shared__ float sB[BN * LDS_PAD];
    float acc[MT * NT * 4];
#pragma unroll
    for (int i = 0; i < MT * NT * 4; i++) acc[i] = 0.f;

    const int row0 = blockIdx.y * 128;
    const int col0 = blockIdx.x * 128;
    gemm_mainloop<BN, WM, WN>(g_O + (size_t)row0 * E_, E_,
                              W + (size_t)col0 * E_, E_, E_, sA, sB, acc);

    const int tid = threadIdx.x;
    const int warp = tid >> 5, lane = tid & 31;
    const int wm = warp % WM, wn = warp / WM;

#pragma unroll
    for (int mt = 0; mt < MT; mt++) {
#pragma unroll
        for (int nt = 0; nt < NT; nt++) {
            const float* c = &acc[(mt * NT + nt) * 4];
            int n = col0 + wn * 32 + nt * 8 + 2 * (lane & 3);
            float b0 = bias[n], b1 = bias[n + 1];
#pragma unroll
            for (int half = 0; half < 2; half++) {
                int m = row0 + wm * 64 + mt * 16 + (lane >> 2) + half * 8;
                float2 v = make_float2(c[half * 2 + 0] + b0, c[half * 2 + 1] + b1);
                *reinterpret_cast<float2*>(&out[(size_t)m * E_ + n]) = v;
            }
        }
    }
}

// ---------------- launch ----------------
extern "C" void kernel_launch(void* const* d_in, const int* in_sizes, int n_in,
                              void* d_out, int out_size) {
    const float* x     = (const float*)d_in[0];
    const void*  mask  = d_in[1];
    const float* prev  = (const float*)d_in[2];
    const float* qkv_w = (const float*)d_in[3];
    const float* qkv_b = (const float*)d_in[4];
    const float* o_w   = (const float*)d_in[5];
    const float* o_b   = (const float*)d_in[6];
    float* out = (float*)d_out;

    detect_mask_kind_kernel<<<1, 32>>>((const unsigned int*)mask);

    qkv_mma_kernel<<<dim3(N3E / 128, (B_ * S_) / 128), 256>>>(x, qkv_w, qkv_b);

    vt_kernel<<<dim3(HD_ / 32, S_ / 32, B_ * H_), dim3(32, 8)>>>();

    scores_mma_kernel<<<dim3(S_ / 128, S_ / 128, B_ * H_), 256>>>(prev, mask);

    softmax_kernel<<<(B_ * H_ * S_) / 8, 256>>>();

    pv_mma_kernel<<<dim3(S_ / 128, B_ * H_), 256>>>();

    out_mma_kernel<<<dim3(E_ / 128, (B_ * S_) / 128), 256>>>(o_w, o_b, out);
}